// round 4
// baseline (speedup 1.0000x reference)
#include <cuda_runtime.h>
#include <cstdint>

// ---------------------------------------------------------------------------
// MinimalQuantumLayer: 4-qubit circuit per 2x2 patch.
//   prep kernel : build 16x16 complex circuit matrix U from q_weights (once).
//   main kernel : per thread, TWO adjacent patches packed as f32x2 lanes:
//                 angles -> poly sin/cos -> v (kron of 4 2-vecs) ->
//                 out = U v (packed FFMA2, matrix broadcast from shared) ->
//                 p = |out|^2 -> <Z_q> via butterfly -> float4 stores.
// ---------------------------------------------------------------------------

__device__ float4 g_M4[256];   // [j*16 + k] = {Re U[k][j], Re, Im U[k][j], Im}

// ---------------- f32x2 packed helpers (sm_103a) ---------------------------
typedef unsigned long long u64x;

__device__ __forceinline__ u64x pack2(float lo, float hi) {
    u64x r;
    asm("mov.b64 %0, {%1, %2};" : "=l"(r)
        : "r"(__float_as_uint(lo)), "r"(__float_as_uint(hi)));
    return r;
}
__device__ __forceinline__ void unpack2(u64x v, float& lo, float& hi) {
    unsigned a, b;
    asm("mov.b64 {%0, %1}, %2;" : "=r"(a), "=r"(b) : "l"(v));
    lo = __uint_as_float(a); hi = __uint_as_float(b);
}
__device__ __forceinline__ u64x bcast2(float f) {
    unsigned u = __float_as_uint(f);
    return ((u64x)u << 32) | (u64x)u;
}
__device__ __forceinline__ u64x fma2(u64x a, u64x b, u64x c) {
    u64x d;
    asm("fma.rn.f32x2 %0, %1, %2, %3;" : "=l"(d) : "l"(a), "l"(b), "l"(c));
    return d;
}
__device__ __forceinline__ u64x mul2(u64x a, u64x b) {
    u64x d;
    asm("mul.rn.f32x2 %0, %1, %2;" : "=l"(d) : "l"(a), "l"(b));
    return d;
}
__device__ __forceinline__ u64x add2(u64x a, u64x b) {
    u64x d;
    asm("add.rn.f32x2 %0, %1, %2;" : "=l"(d) : "l"(a), "l"(b));
    return d;
}
__device__ __forceinline__ u64x neg2(u64x a) { return a ^ 0x8000000080000000ULL; }
__device__ __forceinline__ u64x sub2(u64x a, u64x b) { return add2(a, neg2(b)); }

// sin/cos on [0, pi/4], packed lanes. Taylor deg 8 (cos) / deg 9-ish (sin).
__device__ __forceinline__ void sincos2(u64x t, u64x& c, u64x& s) {
    const u64x ONE = bcast2(1.0f);
    const u64x C2 = bcast2(-0.5f),          C4 = bcast2(1.0f / 24.0f),
               C6 = bcast2(-1.0f / 720.0f), C8 = bcast2(1.0f / 40320.0f);
    const u64x S3 = bcast2(-1.0f / 6.0f),   S5 = bcast2(1.0f / 120.0f),
               S7 = bcast2(-1.0f / 5040.0f);
    u64x t2 = mul2(t, t);
    u64x cp = fma2(C8, t2, C6);
    cp = fma2(cp, t2, C4);
    cp = fma2(cp, t2, C2);
    c  = fma2(cp, t2, ONE);
    u64x sp = fma2(S7, t2, S5);
    sp = fma2(sp, t2, S3);
    sp = fma2(sp, t2, ONE);
    s  = mul2(sp, t);
}

// ---------------- prep: build circuit matrix from q_weights ----------------
// RX(w): [[c, -i s], [-i s, c]] with c=cos(w/2), s=sin(w/2); CNOT ring
// (0,1)(1,2)(2,3)(3,0) per layer. Qubit q bit has value (8 >> q) in index k.
__global__ void qprep_kernel(const float* __restrict__ w) {
    int j = threadIdx.x;
    if (j >= 16) return;
    float sr[16], si[16];
#pragma unroll
    for (int i = 0; i < 16; ++i) { sr[i] = (i == j) ? 1.0f : 0.0f; si[i] = 0.0f; }
#pragma unroll
    for (int l = 0; l < 2; ++l) {
#pragma unroll
        for (int q = 0; q < 4; ++q) {
            float cs, sn;
            sincosf(0.5f * w[l * 4 + q], &sn, &cs);
            const int st = 8 >> q;
#pragma unroll
            for (int i = 0; i < 16; ++i) {
                if (i & st) continue;
                const int i1 = i | st;
                float ar = sr[i], aiv = si[i], br = sr[i1], bi = si[i1];
                sr[i]  = cs * ar + sn * bi;  si[i]  = cs * aiv - sn * br;
                sr[i1] = cs * br + sn * aiv; si[i1] = cs * bi  - sn * ar;
            }
        }
#pragma unroll
        for (int q = 0; q < 4; ++q) {
            const int cm = 8 >> q;
            const int tm = 8 >> ((q + 1) & 3);
            float tr[16], ti[16];
#pragma unroll
            for (int i = 0; i < 16; ++i) {
                const int src = (i & cm) ? (i ^ tm) : i;
                tr[i] = sr[src]; ti[i] = si[src];
            }
#pragma unroll
            for (int i = 0; i < 16; ++i) { sr[i] = tr[i]; si[i] = ti[i]; }
        }
    }
#pragma unroll
    for (int k = 0; k < 16; ++k)
        g_M4[j * 16 + k] = make_float4(sr[k], sr[k], si[k], si[k]);
}

// ---------------- main kernel ---------------------------------------------
// Grid: 262144 threads = 32 (batch) * 128 (rows) * 64 (column pairs).
// Lane lo = patch at column 2*c2, lane hi = patch at column 2*c2+1.
__global__ void __launch_bounds__(256)
qmain_kernel(const float* __restrict__ x, float* __restrict__ out) {
    __shared__ ulonglong2 sM[256];
    const int tid = threadIdx.x;
    sM[tid] = reinterpret_cast<const ulonglong2*>(g_M4)[tid];
    __syncthreads();

    const int idx = blockIdx.x * 256 + tid;
    const int c2 = idx & 63;
    const int r  = (idx >> 6) & 127;
    const int b  = idx >> 13;

    const int xoff = ((b * 256 + 2 * r) * 256) + 4 * c2;
    const float4 p0 = *reinterpret_cast<const float4*>(x + xoff);        // row 2r
    const float4 p1 = *reinterpret_cast<const float4*>(x + xoff + 256);  // row 2r+1

    const u64x PI4 = bcast2(0.78539816339744831f);
    u64x t0 = mul2(pack2(p0.x, p0.z), PI4);   // theta0 (patch A, patch B)
    u64x t1 = mul2(pack2(p0.y, p0.w), PI4);   // theta1
    u64x t2 = mul2(pack2(p1.x, p1.z), PI4);   // theta2
    u64x t3 = mul2(pack2(p1.y, p1.w), PI4);   // theta3

    u64x c0, s0, c1, s1, c2v, s2v, c3, s3;
    sincos2(t0, c0, s0);
    sincos2(t1, c1, s1);
    sincos2(t2, c2v, s2v);
    sincos2(t3, c3, s3);

    u64x q01[4], q23[4];
    q01[0] = mul2(c0, c1); q01[1] = mul2(c0, s1);
    q01[2] = mul2(s0, c1); q01[3] = mul2(s0, s1);
    q23[0] = mul2(c2v, c3); q23[1] = mul2(c2v, s3);
    q23[2] = mul2(s2v, c3); q23[3] = mul2(s2v, s3);

    // out = U v  (packed over two patches), v_j = q01[j>>2]*q23[j&3]
    u64x ar[16], ai[16];
    {
        const u64x vj = mul2(q01[0], q23[0]);
#pragma unroll
        for (int k = 0; k < 16; ++k) {
            const ulonglong2 m = sM[k];
            ar[k] = mul2(m.x, vj);
            ai[k] = mul2(m.y, vj);
        }
    }
#pragma unroll
    for (int j = 1; j < 16; ++j) {
        const u64x vj = mul2(q01[j >> 2], q23[j & 3]);
#pragma unroll
        for (int k = 0; k < 16; ++k) {
            const ulonglong2 m = sM[j * 16 + k];
            ar[k] = fma2(m.x, vj, ar[k]);
            ai[k] = fma2(m.y, vj, ai[k]);
        }
    }

    // probabilities
    u64x p[16];
#pragma unroll
    for (int k = 0; k < 16; ++k)
        p[k] = fma2(ai[k], ai[k], mul2(ar[k], ar[k]));

    // <Z_q> butterflies: sign is (-1)^{bit of k}, bit value 8>>q.
    u64x es[8], ed[8];
#pragma unroll
    for (int m = 0; m < 8; ++m) {
        es[m] = add2(p[2 * m], p[2 * m + 1]);
        ed[m] = sub2(p[2 * m], p[2 * m + 1]);
    }
    const u64x z3 = add2(add2(add2(ed[0], ed[1]), add2(ed[2], ed[3])),
                         add2(add2(ed[4], ed[5]), add2(ed[6], ed[7])));
    u64x fs[4], fd[4];
#pragma unroll
    for (int m = 0; m < 4; ++m) {
        fs[m] = add2(es[2 * m], es[2 * m + 1]);
        fd[m] = sub2(es[2 * m], es[2 * m + 1]);
    }
    const u64x z2 = add2(add2(fd[0], fd[1]), add2(fd[2], fd[3]));
    const u64x z1 = add2(sub2(fs[0], fs[1]), sub2(fs[2], fs[3]));
    const u64x z0 = sub2(add2(fs[0], fs[1]), add2(fs[2], fs[3]));

    float z0a, z0b, z1a, z1b, z2a, z2b, z3a, z3b;
    unpack2(z0, z0a, z0b);
    unpack2(z1, z1a, z1b);
    unpack2(z2, z2a, z2b);
    unpack2(z3, z3a, z3b);

    const int o = ((b * 128 + r) * 128 + 2 * c2) * 4;
    reinterpret_cast<float4*>(out + o)[0] = make_float4(z0a, z1a, z2a, z3a);
    reinterpret_cast<float4*>(out + o)[1] = make_float4(z0b, z1b, z2b, z3b);
}

// ---------------- launch ----------------------------------------------------
extern "C" void kernel_launch(void* const* d_in, const int* in_sizes, int n_in,
                              void* d_out, int out_size) {
    const float* x = (const float*)d_in[0];
    const float* w = (const float*)d_in[1];
    if (n_in >= 2 && in_sizes[0] == 8) {  // defensive: metadata order swap
        const float* t = x; x = w; w = t;
    }
    qprep_kernel<<<1, 16>>>(w);
    qmain_kernel<<<1024, 256>>>(x, (float*)d_out);
}

// round 5
// speedup vs baseline: 1.9410x; 1.9410x over previous
#include <cuda_runtime.h>
#include <cstdint>

// ---------------------------------------------------------------------------
// MinimalQuantumLayer: 4-qubit circuit per 2x2 patch — register-resident
// gate-by-gate simulation, two patches per thread packed as f32x2 lanes.
//
//   angles -> poly sin/cos -> RX layer 1 applied to per-qubit 2-vectors ->
//   complex Kronecker build of 16-amplitude state (all in registers) ->
//   CNOT ring folded into compile-time index permutation ->
//   RX layer 2 as register butterflies -> second CNOT ring folded into
//   probability indexing -> <Z_q> butterfly -> float4 stores.
//
// No shared memory, no prep kernel, no per-element matrix loads.
// ---------------------------------------------------------------------------

typedef unsigned long long u64x;

// ---------------- f32x2 packed helpers (sm_103a) ---------------------------
static __device__ __forceinline__ u64x pack2(float lo, float hi) {
    u64x r;
    asm("mov.b64 %0, {%1, %2};" : "=l"(r)
        : "r"(__float_as_uint(lo)), "r"(__float_as_uint(hi)));
    return r;
}
static __device__ __forceinline__ void unpack2(u64x v, float& lo, float& hi) {
    unsigned a, b;
    asm("mov.b64 {%0, %1}, %2;" : "=r"(a), "=r"(b) : "l"(v));
    lo = __uint_as_float(a); hi = __uint_as_float(b);
}
static __device__ __forceinline__ u64x bcast2(float f) {
    unsigned u = __float_as_uint(f);
    return ((u64x)u << 32) | (u64x)u;
}
static __device__ __forceinline__ u64x fma2(u64x a, u64x b, u64x c) {
    u64x d;
    asm("fma.rn.f32x2 %0, %1, %2, %3;" : "=l"(d) : "l"(a), "l"(b), "l"(c));
    return d;
}
static __device__ __forceinline__ u64x mul2(u64x a, u64x b) {
    u64x d;
    asm("mul.rn.f32x2 %0, %1, %2;" : "=l"(d) : "l"(a), "l"(b));
    return d;
}
static __device__ __forceinline__ u64x add2(u64x a, u64x b) {
    u64x d;
    asm("add.rn.f32x2 %0, %1, %2;" : "=l"(d) : "l"(a), "l"(b));
    return d;
}
static __device__ __forceinline__ u64x neg2(u64x a) { return a ^ 0x8000000080000000ULL; }
static __device__ __forceinline__ u64x sub2(u64x a, u64x b) { return add2(a, neg2(b)); }

// sin/cos on [0, pi/4], packed lanes. Taylor deg 8 (cos) / deg 7 (sin).
static __device__ __forceinline__ void sincos2(u64x t, u64x& c, u64x& s) {
    const u64x ONE = bcast2(1.0f);
    const u64x C2 = bcast2(-0.5f),          C4 = bcast2(1.0f / 24.0f),
               C6 = bcast2(-1.0f / 720.0f), C8 = bcast2(1.0f / 40320.0f);
    const u64x S3 = bcast2(-1.0f / 6.0f),   S5 = bcast2(1.0f / 120.0f),
               S7 = bcast2(-1.0f / 5040.0f);
    u64x t2 = mul2(t, t);
    u64x cp = fma2(C8, t2, C6);
    cp = fma2(cp, t2, C4);
    cp = fma2(cp, t2, C2);
    c  = fma2(cp, t2, ONE);
    u64x sp = fma2(S7, t2, S5);
    sp = fma2(sp, t2, S3);
    sp = fma2(sp, t2, ONE);
    s  = mul2(sp, t);
}

// ---------------- CNOT ring as compile-time index permutation --------------
// CNOT(c=q, t=(q+1)&3): new[i] = old[(i & cm) ? i ^ tm : i]; qubit q bit = 8>>q.
__host__ __device__ constexpr int cnot_f(int i, int q) {
    return (i & (8 >> q)) ? (i ^ (8 >> ((q + 1) & 3))) : i;
}
// Gates applied q=0,1,2,3 => composed lookup f0(f1(f2(f3(i)))).
__host__ __device__ constexpr int ring1(int i) {
    return cnot_f(cnot_f(cnot_f(cnot_f(i, 3), 2), 1), 0);
}
__host__ __device__ constexpr int ring2(int i) { return ring1(ring1(i)); }

// ---------------- main kernel ---------------------------------------------
// Grid: 262144 threads = 32 (batch) * 128 (rows) * 64 (column pairs).
// Lane lo = patch at column 2*c2, lane hi = patch at column 2*c2+1.
__global__ void __launch_bounds__(256, 2)
qmain_kernel(const float* __restrict__ x, const float* __restrict__ w8,
             float* __restrict__ out) {
    // q_weights: 8 warp-uniform floats (row l, qubit q at w[4l+q]).
    float w[8];
    {
        const float4 wa = __ldg(reinterpret_cast<const float4*>(w8));
        const float4 wb = __ldg(reinterpret_cast<const float4*>(w8) + 1);
        w[0] = wa.x; w[1] = wa.y; w[2] = wa.z; w[3] = wa.w;
        w[4] = wb.x; w[5] = wb.y; w[6] = wb.z; w[7] = wb.w;
    }

    const int idx = blockIdx.x * 256 + threadIdx.x;
    const int c2 = idx & 63;
    const int r  = (idx >> 6) & 127;
    const int b  = idx >> 13;

    const int xoff = ((b * 256 + 2 * r) * 256) + 4 * c2;
    const float4 p0 = *reinterpret_cast<const float4*>(x + xoff);        // row 2r
    const float4 p1 = *reinterpret_cast<const float4*>(x + xoff + 256);  // row 2r+1

    const u64x PI4 = bcast2(0.78539816339744831f);
    u64x cq[4], sq[4];
    sincos2(mul2(pack2(p0.x, p0.z), PI4), cq[0], sq[0]);
    sincos2(mul2(pack2(p0.y, p0.w), PI4), cq[1], sq[1]);
    sincos2(mul2(pack2(p1.x, p1.z), PI4), cq[2], sq[2]);
    sincos2(mul2(pack2(p1.y, p1.w), PI4), cq[3], sq[3]);

    // ---- layer-1 RX applied to per-qubit 2-vectors -------------------------
    // RX(w)(c,s)^T = (Cc - iSs, Cs - iSc): re = (Cc, Cs), im = (-Ss, -Sc).
    // |w/2| <= 0.05 -> short Taylor for C,S (err ~2e-11).
    u64x vr[4][2], vi[4][2];
#pragma unroll
    for (int q = 0; q < 4; ++q) {
        const float t = 0.5f * w[q], t2 = t * t;
        const float Cf = 1.0f + t2 * (-0.5f + t2 * (1.0f / 24.0f));
        const float Sf = t * (1.0f + t2 * (-1.0f / 6.0f + t2 * (1.0f / 120.0f)));
        const u64x Cb = bcast2(Cf), nSb = bcast2(-Sf);
        vr[q][0] = mul2(Cb, cq[q]);  vr[q][1] = mul2(Cb, sq[q]);
        vi[q][0] = mul2(nSb, sq[q]); vi[q][1] = mul2(nSb, cq[q]);
    }

    // ---- complex Kronecker build: a = v0 (x) v1, bb = v2 (x) v3 ------------
    u64x ar4[4], ai4[4], br4[4], bi4[4];
#pragma unroll
    for (int i0 = 0; i0 < 2; ++i0) {
        const u64x nvi0 = neg2(vi[0][i0]);
        const u64x nvi2 = neg2(vi[2][i0]);
#pragma unroll
        for (int i1 = 0; i1 < 2; ++i1) {
            const int j = i0 * 2 + i1;
            ar4[j] = fma2(nvi0, vi[1][i1], mul2(vr[0][i0], vr[1][i1]));
            ai4[j] = fma2(vr[0][i0], vi[1][i1], mul2(vi[0][i0], vr[1][i1]));
            br4[j] = fma2(nvi2, vi[3][i1], mul2(vr[2][i0], vr[3][i1]));
            bi4[j] = fma2(vr[2][i0], vi[3][i1], mul2(vi[2][i0], vr[3][i1]));
        }
    }

    // ---- state = a (x) bb : 16 complex amplitudes, all registers -----------
    u64x Sr[16], Si[16];
#pragma unroll
    for (int hi = 0; hi < 4; ++hi) {
        const u64x nai = neg2(ai4[hi]);
#pragma unroll
        for (int lo = 0; lo < 4; ++lo) {
            Sr[hi * 4 + lo] = fma2(nai, bi4[lo], mul2(ar4[hi], br4[lo]));
            Si[hi * 4 + lo] = fma2(ar4[hi], bi4[lo], mul2(ai4[hi], br4[lo]));
        }
    }

    // ---- layer-2 RX gates through ring1 (CNOT ring #1 = free renaming) -----
    // pair (a,b) on qubit q: a'r = C ar + S bi; a'i = C ai - S br;
    //                        b'r = C br + S ai; b'i = C bi - S ar.
#pragma unroll
    for (int q = 0; q < 4; ++q) {
        const float t = 0.5f * w[4 + q], t2 = t * t;
        const float Cf = 1.0f + t2 * (-0.5f + t2 * (1.0f / 24.0f));
        const float Sf = t * (1.0f + t2 * (-1.0f / 6.0f + t2 * (1.0f / 120.0f)));
        const u64x Cb = bcast2(Cf), Sb = bcast2(Sf), nSb = bcast2(-Sf);
        const int st = 8 >> q;
#pragma unroll
        for (int i = 0; i < 16; ++i) {
            if (i & st) continue;
            const int ia = ring1(i);
            const int ib = ring1(i | st);
            const u64x xr = Sr[ia], xi = Si[ia], yr = Sr[ib], yi = Si[ib];
            Sr[ia] = fma2(Cb, xr, mul2(Sb, yi));
            Si[ia] = fma2(Cb, xi, mul2(nSb, yr));
            Sr[ib] = fma2(Cb, yr, mul2(Sb, xi));
            Si[ib] = fma2(Cb, yi, mul2(nSb, xr));
        }
    }

    // ---- probabilities through ring2 (CNOT ring #2 = free renaming) --------
    u64x p[16];
#pragma unroll
    for (int j = 0; j < 16; ++j) {
        const int pj = ring2(j);
        p[j] = fma2(Si[pj], Si[pj], mul2(Sr[pj], Sr[pj]));
    }

    // ---- <Z_q> butterflies: sign = (-1)^{bit (8>>q) of j} -------------------
    u64x es[8], ed[8];
#pragma unroll
    for (int m = 0; m < 8; ++m) {
        es[m] = add2(p[2 * m], p[2 * m + 1]);
        ed[m] = sub2(p[2 * m], p[2 * m + 1]);
    }
    const u64x z3 = add2(add2(add2(ed[0], ed[1]), add2(ed[2], ed[3])),
                         add2(add2(ed[4], ed[5]), add2(ed[6], ed[7])));
    u64x fs[4], fd[4];
#pragma unroll
    for (int m = 0; m < 4; ++m) {
        fs[m] = add2(es[2 * m], es[2 * m + 1]);
        fd[m] = sub2(es[2 * m], es[2 * m + 1]);
    }
    const u64x z2 = add2(add2(fd[0], fd[1]), add2(fd[2], fd[3]));
    const u64x z1 = add2(sub2(fs[0], fs[1]), sub2(fs[2], fs[3]));
    const u64x z0 = sub2(add2(fs[0], fs[1]), add2(fs[2], fs[3]));

    float z0a, z0b, z1a, z1b, z2a, z2b, z3a, z3b;
    unpack2(z0, z0a, z0b);
    unpack2(z1, z1a, z1b);
    unpack2(z2, z2a, z2b);
    unpack2(z3, z3a, z3b);

    const int o = ((b * 128 + r) * 128 + 2 * c2) * 4;
    reinterpret_cast<float4*>(out + o)[0] = make_float4(z0a, z1a, z2a, z3a);
    reinterpret_cast<float4*>(out + o)[1] = make_float4(z0b, z1b, z2b, z3b);
}

// ---------------- launch ----------------------------------------------------
extern "C" void kernel_launch(void* const* d_in, const int* in_sizes, int n_in,
                              void* d_out, int out_size) {
    const float* x = (const float*)d_in[0];
    const float* w = (const float*)d_in[1];
    if (n_in >= 2 && in_sizes[0] == 8) {  // defensive: metadata order swap
        const float* t = x; x = w; w = t;
    }
    qmain_kernel<<<1024, 256>>>(x, w, (float*)d_out);
}